// round 1
// baseline (speedup 1.0000x reference)
#include <cuda_runtime.h>
#include <cstdint>

// RNG scheme: 1 = jax_threefry_partitionable (default in modern JAX),
//             0 = legacy "original" threefry counter layout.
#ifndef RNG_PARTITIONABLE
#define RNG_PARTITIONABLE 1
#endif

#define SDIM 16
#define HDIM 128
#define HH 96
#define WW 96
#define NB 8
#define PLANE (HH * WW)            // 9216
#define FRAME (NB * SDIM * PLANE)  // 1179648
#define HALF (FRAME / 2)

// scratch for pre-gating updated state (x_mid)
__device__ float g_xmid[FRAME];

// ---------------------------------------------------------------------------
// Threefry-2x32 (exactly JAX's 20-round schedule)
// ---------------------------------------------------------------------------
__host__ __device__ __forceinline__ void threefry2x32(
    uint32_t k0, uint32_t k1, uint32_t x0, uint32_t x1,
    uint32_t &o0, uint32_t &o1)
{
  uint32_t ks2 = k0 ^ k1 ^ 0x1BD11BDAu;
  x0 += k0; x1 += k1;
#define TFR(r) { x0 += x1; x1 = (x1 << (r)) | (x1 >> (32 - (r))); x1 ^= x0; }
  TFR(13) TFR(15) TFR(26) TFR(6)
  x0 += k1; x1 += ks2 + 1u;
  TFR(17) TFR(29) TFR(16) TFR(24)
  x0 += ks2; x1 += k0 + 2u;
  TFR(13) TFR(15) TFR(26) TFR(6)
  x0 += k0; x1 += k1 + 3u;
  TFR(17) TFR(29) TFR(16) TFR(24)
  x0 += k1; x1 += ks2 + 4u;
  TFR(13) TFR(15) TFR(26) TFR(6)
  x0 += ks2; x1 += k0 + 5u;
#undef TFR
  o0 = x0; o1 = x1;
}

__device__ __forceinline__ uint32_t rng_bits(uint32_t k0, uint32_t k1, uint32_t idx)
{
#if RNG_PARTITIONABLE
  uint32_t o0, o1;
  threefry2x32(k0, k1, 0u, idx, o0, o1);
  return o0 ^ o1;
#else
  uint32_t o0, o1;
  if (idx < HALF) { threefry2x32(k0, k1, idx, idx + (uint32_t)HALF, o0, o1); return o0; }
  else            { threefry2x32(k0, k1, idx - (uint32_t)HALF, idx, o0, o1); return o1; }
#endif
}

// ---------------------------------------------------------------------------
// stepA: per-pixel perception + 48->128 relu + 128->16, stochastic update.
// Writes x_mid = x + mask * update(x) into g_xmid.
// ---------------------------------------------------------------------------
#define XS_FLOATS (SDIM * 18 * 18)                 // 5184
#define W2_FLOATS (HDIM * 48)                      // 6144
#define W3_FLOATS (SDIM * HDIM)                    // 2048
#define SMEM_FLOATS (XS_FLOATS + W2_FLOATS + W3_FLOATS)
#define SMEM_BYTES (SMEM_FLOATS * 4)

extern "C" __global__ void __launch_bounds__(256, 2)
stepA(const float* __restrict__ xin,
      const float* __restrict__ w2,
      const float* __restrict__ w3,
      uint32_t k0, uint32_t k1)
{
  extern __shared__ float sm[];
  float* xs  = sm;                    // [16][18][18]
  float* w2s = sm + XS_FLOATS;        // [128][48]
  float* w3s = w2s + W2_FLOATS;       // [16][128]

  const int tx = threadIdx.x, ty = threadIdx.y;
  const int tid = ty * 16 + tx;
  const int b  = blockIdx.z;
  const int h0 = blockIdx.y * 16;
  const int w0 = blockIdx.x * 16;

  // cooperative load of w2 / w3 (vectorized)
  {
    const float4* g2 = (const float4*)w2;
    float4* s2 = (float4*)w2s;
#pragma unroll
    for (int i = 0; i < 6; i++) s2[tid + i * 256] = g2[tid + i * 256];   // 1536 x float4
    const float4* g3 = (const float4*)w3;
    float4* s3 = (float4*)w3s;
#pragma unroll
    for (int i = 0; i < 2; i++) s3[tid + i * 256] = g3[tid + i * 256];   // 512 x float4
  }

  // load x tile with 1-px halo, zero padding (conv semantics)
  const float* xb = xin + (size_t)b * SDIM * PLANE;
  for (int i = tid; i < XS_FLOATS; i += 256) {
    int c = i / 324;
    int rem = i - c * 324;
    int r = rem / 18;
    int q = rem - r * 18;
    int gh = h0 - 1 + r, gw = w0 - 1 + q;
    float v = 0.f;
    if ((unsigned)gh < HH && (unsigned)gw < WW)
      v = xb[c * PLANE + gh * WW + gw];
    xs[i] = v;
  }
  __syncthreads();

  // perception: y[3c] = x, y[3c+1] = sobel-x, y[3c+2] = sobel-y
  float y[48];
#pragma unroll
  for (int c = 0; c < SDIM; c++) {
    const float* p = xs + c * 324 + ty * 18 + tx;
    float a00 = p[0],  a01 = p[1],  a02 = p[2];
    float a10 = p[18], a11 = p[19], a12 = p[20];
    float a20 = p[36], a21 = p[37], a22 = p[38];
    y[3 * c]     = a11;
    y[3 * c + 1] = ((a02 - a00) + 2.f * (a12 - a10) + (a22 - a20)) * 0.125f;
    y[3 * c + 2] = ((a20 - a00) + 2.f * (a21 - a01) + (a22 - a02)) * 0.125f;
  }

  float d[16];
#pragma unroll
  for (int c = 0; c < 16; c++) d[c] = 0.f;

  // fused (128x48)@y -> relu -> (16x128)@h, 4 hidden units at a time
#pragma unroll 1
  for (int o = 0; o < HDIM; o += 4) {
    const float4* r0 = (const float4*)(w2s + (o + 0) * 48);
    const float4* r1 = (const float4*)(w2s + (o + 1) * 48);
    const float4* r2 = (const float4*)(w2s + (o + 2) * 48);
    const float4* r3 = (const float4*)(w2s + (o + 3) * 48);
    float h0a = 0.f, h1a = 0.f, h2a = 0.f, h3a = 0.f;
#pragma unroll
    for (int kq = 0; kq < 12; kq++) {
      float4 a0 = r0[kq], a1 = r1[kq], a2 = r2[kq], a3 = r3[kq];
      float y0 = y[4 * kq], y1 = y[4 * kq + 1], y2 = y[4 * kq + 2], y3 = y[4 * kq + 3];
      h0a = fmaf(a0.x, y0, h0a); h0a = fmaf(a0.y, y1, h0a);
      h0a = fmaf(a0.z, y2, h0a); h0a = fmaf(a0.w, y3, h0a);
      h1a = fmaf(a1.x, y0, h1a); h1a = fmaf(a1.y, y1, h1a);
      h1a = fmaf(a1.z, y2, h1a); h1a = fmaf(a1.w, y3, h1a);
      h2a = fmaf(a2.x, y0, h2a); h2a = fmaf(a2.y, y1, h2a);
      h2a = fmaf(a2.z, y2, h2a); h2a = fmaf(a2.w, y3, h2a);
      h3a = fmaf(a3.x, y0, h3a); h3a = fmaf(a3.y, y1, h3a);
      h3a = fmaf(a3.z, y2, h3a); h3a = fmaf(a3.w, y3, h3a);
    }
    h0a = fmaxf(h0a, 0.f); h1a = fmaxf(h1a, 0.f);
    h2a = fmaxf(h2a, 0.f); h3a = fmaxf(h3a, 0.f);
#pragma unroll
    for (int c = 0; c < 16; c++) {
      float4 w = *(const float4*)(w3s + c * HDIM + o);
      d[c] = fmaf(w.x, h0a, d[c]); d[c] = fmaf(w.y, h1a, d[c]);
      d[c] = fmaf(w.z, h2a, d[c]); d[c] = fmaf(w.w, h3a, d[c]);
    }
  }

  // stochastic update mask (JAX threefry) + write x_mid
  const int hp = h0 + ty, wp = w0 + tx;
  const uint32_t base = ((uint32_t)b * SDIM) * PLANE + (uint32_t)(hp * WW + wp);
#pragma unroll 1
  for (int c = 0; c < 16; c++) {
    uint32_t idx = base + (uint32_t)c * PLANE;
    uint32_t bits = rng_bits(k0, k1, idx);
    float u = __uint_as_float((bits >> 9) | 0x3f800000u) - 1.0f;
    float v = y[3 * c] + ((u > 0.5f) ? d[c] : 0.f);
    g_xmid[idx] = v;
  }
}

// ---------------------------------------------------------------------------
// stepB: alive gating (maxpool3 > 0.1 on alpha, pre & post) + frame write.
// ---------------------------------------------------------------------------
extern "C" __global__ void __launch_bounds__(256)
stepB(const float* __restrict__ xprev, float* __restrict__ xout)
{
  int p = blockIdx.x * 256 + threadIdx.x;  // over (b, h, w)
  if (p >= NB * PLANE) return;
  int b = p / PLANE;
  int hw = p - b * PLANE;
  int h = hw / WW, w = hw - h * WW;

  const float* prevA = xprev + ((size_t)b * SDIM + 3) * PLANE;
  const float* midA  = g_xmid + ((size_t)b * SDIM + 3) * PLANE;

  float m1 = -1e30f, m2 = -1e30f;
#pragma unroll
  for (int di = -1; di <= 1; di++) {
    int hh = h + di;
    if ((unsigned)hh >= HH) continue;
#pragma unroll
    for (int dj = -1; dj <= 1; dj++) {
      int wq = w + dj;
      if ((unsigned)wq >= WW) continue;
      int o = hh * WW + wq;
      m1 = fmaxf(m1, prevA[o]);
      m2 = fmaxf(m2, midA[o]);
    }
  }
  float gate = (m1 > 0.1f && m2 > 0.1f) ? 1.f : 0.f;

  size_t base = (size_t)b * SDIM * PLANE + (size_t)hw;
#pragma unroll
  for (int c = 0; c < 16; c++)
    xout[base + c * PLANE] = g_xmid[base + c * PLANE] * gate;
}

// ---------------------------------------------------------------------------
// kernel_launch: 24 sequential (stepA, stepB) pairs on the capture stream.
// Subkeys computed on host (pure CPU arithmetic, deterministic).
// ---------------------------------------------------------------------------
extern "C" void kernel_launch(void* const* d_in, const int* in_sizes, int n_in,
                              void* d_out, int out_size)
{
  const float* x0 = (const float*)d_in[0];
  // d_in[1] = num_steps (device scalar; we derive it from out_size instead)
  const float* w2 = (const float*)d_in[3];
  const float* w3 = (const float*)d_in[4];
  float* out = (float*)d_out;

  const int nsteps = out_size / FRAME;

  cudaFuncSetAttribute(stepA, cudaFuncAttributeMaxDynamicSharedMemorySize, SMEM_BYTES);

  for (int t = 0; t < nsteps; t++) {
    uint32_t sk0, sk1;
#if RNG_PARTITIONABLE
    // split_foldlike: key_t = threefry2x32((0,42), (0, t))
    threefry2x32(0u, 42u, 0u, (uint32_t)t, sk0, sk1);
#else
    // original split: counts = iota(2n); halves pair (j, j+n); flat = [o0s, o1s]
    {
      uint32_t n = (uint32_t)nsteps;
      uint32_t i0 = 2u * (uint32_t)t, i1 = i0 + 1u;
      uint32_t a, bq;
      if (i0 < n) { threefry2x32(0u, 42u, i0, i0 + n, a, bq); sk0 = a; }
      else        { threefry2x32(0u, 42u, i0 - n, i0, a, bq); sk0 = bq; }
      if (i1 < n) { threefry2x32(0u, 42u, i1, i1 + n, a, bq); sk1 = a; }
      else        { threefry2x32(0u, 42u, i1 - n, i1, a, bq); sk1 = bq; }
    }
#endif
    const float* cur = (t == 0) ? x0 : out + (size_t)(t - 1) * FRAME;
    stepA<<<dim3(6, 6, NB), dim3(16, 16), SMEM_BYTES>>>(cur, w2, w3, sk0, sk1);
    stepB<<<(NB * PLANE + 255) / 256, 256>>>(cur, out + (size_t)t * FRAME);
  }
}

// round 2
// speedup vs baseline: 1.2121x; 1.2121x over previous
#include <cuda_runtime.h>
#include <cstdint>

#define SDIM 16
#define HDIM 128
#define HH 96
#define WW 96
#define NB 8
#define PLANE (HH * WW)            // 9216
#define FRAME (NB * SDIM * PLANE)  // 1179648

// ping-pong scratch: pre-gating updated state and alive_pre planes
__device__ float g_mid[2][FRAME];
__device__ float g_pre[2][NB * PLANE];

// ---------------------------------------------------------------------------
// Threefry-2x32 (JAX 20-round schedule), partitionable scheme
// ---------------------------------------------------------------------------
__host__ __device__ __forceinline__ void threefry2x32(
    uint32_t k0, uint32_t k1, uint32_t x0, uint32_t x1,
    uint32_t &o0, uint32_t &o1)
{
  uint32_t ks2 = k0 ^ k1 ^ 0x1BD11BDAu;
  x0 += k0; x1 += k1;
#define TFR(r) { x0 += x1; x1 = (x1 << (r)) | (x1 >> (32 - (r))); x1 ^= x0; }
  TFR(13) TFR(15) TFR(26) TFR(6)
  x0 += k1; x1 += ks2 + 1u;
  TFR(17) TFR(29) TFR(16) TFR(24)
  x0 += ks2; x1 += k0 + 2u;
  TFR(13) TFR(15) TFR(26) TFR(6)
  x0 += k0; x1 += k1 + 3u;
  TFR(17) TFR(29) TFR(16) TFR(24)
  x0 += k1; x1 += ks2 + 4u;
  TFR(13) TFR(15) TFR(26) TFR(6)
  x0 += ks2; x1 += k0 + 5u;
#undef TFR
  o0 = x0; o1 = x1;
}

// ---------------------------------------------------------------------------
// packed f32x2 helpers (Blackwell FFMA2 — 2 fp32 FMAs per instruction)
// ---------------------------------------------------------------------------
typedef unsigned long long u64;

__device__ __forceinline__ void ffma2(u64 &acc, u64 a, u64 b) {
  asm("fma.rn.f32x2 %0, %1, %2, %0;" : "+l"(acc) : "l"(a), "l"(b));
}
__device__ __forceinline__ u64 pk(float lo, float hi) {
  u64 r; asm("mov.b64 %0, {%1, %2};" : "=l"(r) : "f"(lo), "f"(hi)); return r;
}
__device__ __forceinline__ float2 unpk(u64 v) {
  float2 r; asm("mov.b64 {%0, %1}, %2;" : "=f"(r.x), "=f"(r.y) : "l"(v)); return r;
}

// ---------------------------------------------------------------------------
// stepA (fused): gate previous mid -> x_t (also emits frame t-1), perception,
// 48->128 relu -> 128->16 with packed FFMA2, threefry mask, write mid_t + pre_t.
// ---------------------------------------------------------------------------
#define XS_FLOATS (SDIM * 18 * 18)   // 5184
#define W2_FLOATS (HDIM * 48)        // 6144
#define W3_FLOATS (SDIM * HDIM)     // 2048
#define MIDA_FLOATS 400              // 20x20 mid-alpha halo
#define PREB_FLOATS 324              // 18x18 alive_pre
#define GA_FLOATS 324                // 18x18 gate
#define SMEM_FLOATS (XS_FLOATS + W2_FLOATS + W3_FLOATS + MIDA_FLOATS + PREB_FLOATS + GA_FLOATS)
#define SMEM_BYTES (SMEM_FLOATS * 4)

extern "C" __global__ void __launch_bounds__(256, 2)
stepA(const float* __restrict__ x0in,
      const float* __restrict__ w2,
      const float* __restrict__ w3,
      float* __restrict__ frame_prev,   // out + (t-1)*FRAME (valid for t>0)
      int t, uint32_t k0, uint32_t k1)
{
  extern __shared__ float sm[];
  float* xs   = sm;                          // [16][18][18] gated x_t tile
  float* w2s  = xs + XS_FLOATS;              // [128][48]
  float* w3s  = w2s + W2_FLOATS;             // [16][128]
  float* midA = w3s + W3_FLOATS;             // [20][20]
  float* preb = midA + MIDA_FLOATS;          // [18][18]
  float* ga   = preb + PREB_FLOATS;          // [18][18]

  const int tx = threadIdx.x, ty = threadIdx.y;
  const int tid = ty * 16 + tx;
  const int b  = blockIdx.z;
  const int bh = blockIdx.y * 16;
  const int bw = blockIdx.x * 16;
  const int wb = t & 1;          // write buffer
  const int rb = 1 - wb;         // read buffer (mid_{t-1})

  // ---- RNG mask first: independent long ALU chains overlap tile loads ----
  uint32_t mask = 0;
  {
    const uint32_t basei = (uint32_t)b * SDIM * PLANE
                         + (uint32_t)((bh + ty) * WW + (bw + tx));
#pragma unroll 4
    for (int c = 0; c < 16; c++) {
      uint32_t o0, o1;
      threefry2x32(k0, k1, 0u, basei + (uint32_t)c * PLANE, o0, o1);
      uint32_t bits = o0 ^ o1;
      if ((bits >> 9) > 0x400000u) mask |= (1u << c);  // uniform > 0.5 exactly
    }
  }

  // ---- cooperative loads: weights, mid-alpha halo, alive_pre ----
  {
    const float4* g2 = (const float4*)w2;
    float4* s2 = (float4*)w2s;
#pragma unroll
    for (int i = 0; i < 6; i++) s2[tid + i * 256] = g2[tid + i * 256];
    const float4* g3 = (const float4*)w3;
    float4* s3 = (float4*)w3s;
#pragma unroll
    for (int i = 0; i < 2; i++) s3[tid + i * 256] = g3[tid + i * 256];
  }
  if (t > 0) {
    const float* aplane = g_mid[rb] + ((size_t)b * SDIM + 3) * PLANE;
    for (int i = tid; i < MIDA_FLOATS; i += 256) {
      int rr = i / 20, qq = i - rr * 20;
      int gh = bh - 2 + rr, gw = bw - 2 + qq;
      midA[i] = ((unsigned)gh < HH && (unsigned)gw < WW)
                ? aplane[gh * WW + gw] : -1e30f;
    }
    const float* prer = g_pre[rb] + (size_t)b * PLANE;
    for (int i = tid; i < PREB_FLOATS; i += 256) {
      int rr = i / 18, qq = i - rr * 18;
      int gh = bh - 1 + rr, gw = bw - 1 + qq;
      preb[i] = ((unsigned)gh < HH && (unsigned)gw < WW)
                ? prer[gh * WW + gw] : 0.f;
    }
  }
  __syncthreads();

  // ---- gate = alive_pre & (maxpool3(mid alpha) > 0.1), on the 18x18 ring ----
  if (t > 0) {
    for (int i = tid; i < GA_FLOATS; i += 256) {
      int rr = i / 18, qq = i - rr * 18;
      float m = -1e30f;
#pragma unroll
      for (int dr = 0; dr < 3; dr++)
#pragma unroll
        for (int dq = 0; dq < 3; dq++)
          m = fmaxf(m, midA[(rr + dr) * 20 + qq + dq]);
      ga[i] = (preb[i] != 0.f && m > 0.1f) ? 1.f : 0.f;
    }
  }
  __syncthreads();

  // ---- build x_t tile (gated); interior also written as frame t-1 ----
  const float* srcb = (t == 0)
      ? (x0in + (size_t)b * SDIM * PLANE)
      : (g_mid[rb] + (size_t)b * SDIM * PLANE);
  for (int i = tid; i < XS_FLOATS; i += 256) {
    int c = i / 324;
    int rem = i - c * 324;
    int r = rem / 18, q = rem - r * 18;
    int gh = bh - 1 + r, gw = bw - 1 + q;
    float v = 0.f;
    if ((unsigned)gh < HH && (unsigned)gw < WW) {
      size_t gi = (size_t)c * PLANE + gh * WW + gw;
      v = srcb[gi];
      if (t > 0) {
        v *= ga[rem];
        if ((unsigned)(r - 1) < 16u && (unsigned)(q - 1) < 16u)
          frame_prev[(size_t)b * SDIM * PLANE + gi] = v;
      }
    }
    xs[i] = v;
  }
  __syncthreads();

  // ---- alive_pre for this step (from gated x_t alpha) ----
  const uint32_t pix = (uint32_t)((bh + ty) * WW + (bw + tx));
  {
    const float* pa = xs + 3 * 324;
    float m = -1e30f;
#pragma unroll
    for (int dr = 0; dr < 3; dr++)
#pragma unroll
      for (int dq = 0; dq < 3; dq++)
        m = fmaxf(m, pa[(ty + dr) * 18 + tx + dq]);
    g_pre[wb][(size_t)b * PLANE + pix] = (m > 0.1f) ? 1.f : 0.f;
  }

  // ---- perception: identity, sobel-x, sobel-y per channel ----
  float y[48];
#pragma unroll
  for (int c = 0; c < SDIM; c++) {
    const float* p = xs + c * 324 + ty * 18 + tx;
    float a00 = p[0],  a01 = p[1],  a02 = p[2];
    float a10 = p[18], a11 = p[19], a12 = p[20];
    float a20 = p[36], a21 = p[37], a22 = p[38];
    y[3 * c]     = a11;
    y[3 * c + 1] = ((a02 - a00) + 2.f * (a12 - a10) + (a22 - a20)) * 0.125f;
    y[3 * c + 2] = ((a20 - a00) + 2.f * (a21 - a01) + (a22 - a02)) * 0.125f;
  }
  u64 Y[24];
#pragma unroll
  for (int i = 0; i < 24; i++) Y[i] = pk(y[2 * i], y[2 * i + 1]);

  // ---- fused matvecs with packed FFMA2 ----
  u64 D[16];
#pragma unroll
  for (int c = 0; c < 16; c++) D[c] = 0ull;

#pragma unroll 1
  for (int o = 0; o < HDIM; o += 4) {
    const ulonglong2* r0 = (const ulonglong2*)(w2s + (o + 0) * 48);
    const ulonglong2* r1 = (const ulonglong2*)(w2s + (o + 1) * 48);
    const ulonglong2* r2 = (const ulonglong2*)(w2s + (o + 2) * 48);
    const ulonglong2* r3 = (const ulonglong2*)(w2s + (o + 3) * 48);
    u64 a0 = 0ull, a1 = 0ull, a2 = 0ull, a3 = 0ull;
#pragma unroll
    for (int kq = 0; kq < 12; kq++) {
      ulonglong2 b0 = r0[kq], b1 = r1[kq], b2 = r2[kq], b3 = r3[kq];
      u64 yl = Y[2 * kq], yh = Y[2 * kq + 1];
      ffma2(a0, b0.x, yl); ffma2(a0, b0.y, yh);
      ffma2(a1, b1.x, yl); ffma2(a1, b1.y, yh);
      ffma2(a2, b2.x, yl); ffma2(a2, b2.y, yh);
      ffma2(a3, b3.x, yl); ffma2(a3, b3.y, yh);
    }
    float2 f0 = unpk(a0), f1 = unpk(a1), f2 = unpk(a2), f3 = unpk(a3);
    float h0a = fmaxf(f0.x + f0.y, 0.f);
    float h1a = fmaxf(f1.x + f1.y, 0.f);
    float h2a = fmaxf(f2.x + f2.y, 0.f);
    float h3a = fmaxf(f3.x + f3.y, 0.f);
    u64 H0 = pk(h0a, h1a), H1 = pk(h2a, h3a);
#pragma unroll
    for (int c = 0; c < 16; c++) {
      ulonglong2 w = *(const ulonglong2*)(w3s + c * HDIM + o);
      ffma2(D[c], w.x, H0);
      ffma2(D[c], w.y, H1);
    }
  }

  // ---- stochastic update, write mid_t ----
  float* midw = g_mid[wb] + (size_t)b * SDIM * PLANE;
#pragma unroll
  for (int c = 0; c < 16; c++) {
    float2 dd = unpk(D[c]);
    float dv = dd.x + dd.y;
    float xid = xs[c * 324 + (ty + 1) * 18 + (tx + 1)];
    float v = xid + (((mask >> c) & 1u) ? dv : 0.f);
    midw[(size_t)c * PLANE + pix] = v;
  }
}

// ---------------------------------------------------------------------------
// stepC: gate and emit the final frame.
// ---------------------------------------------------------------------------
extern "C" __global__ void __launch_bounds__(256)
stepC(float* __restrict__ outf, int pb)
{
  int p = blockIdx.x * 256 + threadIdx.x;
  if (p >= NB * PLANE) return;
  int b = p / PLANE;
  int hw = p - b * PLANE;
  int h = hw / WW, w = hw - h * WW;

  const float* mida = g_mid[pb] + ((size_t)b * SDIM + 3) * PLANE;
  float m = -1e30f;
#pragma unroll
  for (int di = -1; di <= 1; di++) {
    int hh = h + di;
    if ((unsigned)hh >= HH) continue;
#pragma unroll
    for (int dj = -1; dj <= 1; dj++) {
      int wq = w + dj;
      if ((unsigned)wq >= WW) continue;
      m = fmaxf(m, mida[hh * WW + wq]);
    }
  }
  float gate = (g_pre[pb][p] != 0.f && m > 0.1f) ? 1.f : 0.f;

  size_t base = (size_t)b * SDIM * PLANE + (size_t)hw;
#pragma unroll
  for (int c = 0; c < 16; c++)
    outf[base + c * PLANE] = g_mid[pb][base + c * PLANE] * gate;
}

// ---------------------------------------------------------------------------
// kernel_launch
// ---------------------------------------------------------------------------
extern "C" void kernel_launch(void* const* d_in, const int* in_sizes, int n_in,
                              void* d_out, int out_size)
{
  const float* x0 = (const float*)d_in[0];
  const float* w2 = (const float*)d_in[3];
  const float* w3 = (const float*)d_in[4];
  float* out = (float*)d_out;

  const int nsteps = out_size / FRAME;

  cudaFuncSetAttribute(stepA, cudaFuncAttributeMaxDynamicSharedMemorySize, SMEM_BYTES);

  for (int t = 0; t < nsteps; t++) {
    uint32_t sk0, sk1;
    threefry2x32(0u, 42u, 0u, (uint32_t)t, sk0, sk1);   // key_t = fold(key42, t)
    float* fprev = out + (size_t)(t > 0 ? t - 1 : 0) * FRAME;
    stepA<<<dim3(6, 6, NB), dim3(16, 16), SMEM_BYTES>>>(x0, w2, w3, fprev, t, sk0, sk1);
  }
  stepC<<<(NB * PLANE + 255) / 256, 256>>>(out + (size_t)(nsteps - 1) * FRAME,
                                           (nsteps - 1) & 1);
}

// round 3
// speedup vs baseline: 1.3123x; 1.0827x over previous
#include <cuda_runtime.h>
#include <cstdint>

#define SDIM 16
#define HDIM 128
#define HH 96
#define WW 96
#define NB 8
#define PLANE (HH * WW)            // 9216
#define FRAME (NB * SDIM * PLANE)  // 1179648

// ping-pong scratch: pre-gating updated state and alive_pre planes
__device__ float g_mid[2][FRAME];
__device__ float g_pre[2][NB * PLANE];

// ---------------------------------------------------------------------------
// Threefry-2x32 (JAX 20-round schedule), partitionable scheme
// ---------------------------------------------------------------------------
__host__ __device__ __forceinline__ void threefry2x32(
    uint32_t k0, uint32_t k1, uint32_t x0, uint32_t x1,
    uint32_t &o0, uint32_t &o1)
{
  uint32_t ks2 = k0 ^ k1 ^ 0x1BD11BDAu;
  x0 += k0; x1 += k1;
#define TFR(r) { x0 += x1; x1 = (x1 << (r)) | (x1 >> (32 - (r))); x1 ^= x0; }
  TFR(13) TFR(15) TFR(26) TFR(6)
  x0 += k1; x1 += ks2 + 1u;
  TFR(17) TFR(29) TFR(16) TFR(24)
  x0 += ks2; x1 += k0 + 2u;
  TFR(13) TFR(15) TFR(26) TFR(6)
  x0 += k0; x1 += k1 + 3u;
  TFR(17) TFR(29) TFR(16) TFR(24)
  x0 += k1; x1 += ks2 + 4u;
  TFR(13) TFR(15) TFR(26) TFR(6)
  x0 += ks2; x1 += k0 + 5u;
#undef TFR
  o0 = x0; o1 = x1;
}

// ---------------------------------------------------------------------------
// packed f32x2 helpers (Blackwell FFMA2)
// ---------------------------------------------------------------------------
typedef unsigned long long u64;

__device__ __forceinline__ void ffma2(u64 &acc, u64 a, u64 b) {
  asm("fma.rn.f32x2 %0, %1, %2, %0;" : "+l"(acc) : "l"(a), "l"(b));
}
__device__ __forceinline__ u64 pk(float lo, float hi) {
  u64 r; asm("mov.b64 %0, {%1, %2};" : "=l"(r) : "f"(lo), "f"(hi)); return r;
}
__device__ __forceinline__ float2 unpk(u64 v) {
  float2 r; asm("mov.b64 {%0, %1}, %2;" : "=f"(r.x), "=f"(r.y) : "l"(v)); return r;
}

// ---------------------------------------------------------------------------
// stepA (fused, 2 pixels/thread): gate previous mid -> x_t (emits frame t-1),
// perception, 48->128 relu -> 128->16 packed FFMA2, threefry mask, write mid_t.
// Block: 128 threads (16 x 8); thread handles tile rows ty and ty+8.
// ---------------------------------------------------------------------------
#define XS_FLOATS (SDIM * 18 * 18)   // 5184
#define W2_FLOATS (HDIM * 48)        // 6144
#define W3_FLOATS (SDIM * HDIM)      // 2048
#define MIDA_FLOATS 400              // 20x20 mid-alpha halo
#define PREB_FLOATS 324              // 18x18 alive_pre
#define GA_FLOATS 324                // 18x18 gate
#define SMEM_FLOATS (XS_FLOATS + W2_FLOATS + W3_FLOATS + MIDA_FLOATS + PREB_FLOATS + GA_FLOATS)
#define SMEM_BYTES (SMEM_FLOATS * 4)
#define NTHR 128

extern "C" __global__ void __launch_bounds__(NTHR)
stepA(const float* __restrict__ x0in,
      const float* __restrict__ w2,
      const float* __restrict__ w3,
      float* __restrict__ frame_prev,   // out + (t-1)*FRAME (valid for t>0)
      int t, uint32_t k0, uint32_t k1)
{
  extern __shared__ float sm[];
  float* xs   = sm;                          // [16][18][18] gated x_t tile
  float* w2s  = xs + XS_FLOATS;              // [128][48]
  float* w3s  = w2s + W2_FLOATS;             // [16][128]
  float* midA = w3s + W3_FLOATS;             // [20][20]
  float* preb = midA + MIDA_FLOATS;          // [18][18]
  float* ga   = preb + PREB_FLOATS;          // [18][18]

  const int tx = threadIdx.x, ty = threadIdx.y;   // ty in [0,8)
  const int tid = ty * 16 + tx;
  const int b  = blockIdx.z;
  const int bh = blockIdx.y * 16;
  const int bw = blockIdx.x * 16;
  const int wb = t & 1;          // write buffer
  const int rb = 1 - wb;         // read buffer (mid_{t-1})

  // ---- RNG masks first: long independent ALU chains overlap tile loads ----
  uint32_t maskA = 0, maskB = 0;
  {
    const uint32_t baseA = (uint32_t)b * SDIM * PLANE
                         + (uint32_t)((bh + ty) * WW + (bw + tx));
    const uint32_t baseB = baseA + 8u * WW;
#pragma unroll 4
    for (int c = 0; c < 16; c++) {
      uint32_t o0, o1;
      threefry2x32(k0, k1, 0u, baseA + (uint32_t)c * PLANE, o0, o1);
      if (((o0 ^ o1) >> 9) > 0x400000u) maskA |= (1u << c);
      threefry2x32(k0, k1, 0u, baseB + (uint32_t)c * PLANE, o0, o1);
      if (((o0 ^ o1) >> 9) > 0x400000u) maskB |= (1u << c);
    }
  }

  // ---- cooperative loads: weights, mid-alpha halo, alive_pre ----
  {
    const float4* g2 = (const float4*)w2;
    float4* s2 = (float4*)w2s;
#pragma unroll
    for (int i = 0; i < 12; i++) s2[tid + i * NTHR] = g2[tid + i * NTHR];  // 1536
    const float4* g3 = (const float4*)w3;
    float4* s3 = (float4*)w3s;
#pragma unroll
    for (int i = 0; i < 4; i++) s3[tid + i * NTHR] = g3[tid + i * NTHR];   // 512
  }
  if (t > 0) {
    const float* aplane = g_mid[rb] + ((size_t)b * SDIM + 3) * PLANE;
    for (int i = tid; i < MIDA_FLOATS; i += NTHR) {
      int rr = i / 20, qq = i - rr * 20;
      int gh = bh - 2 + rr, gw = bw - 2 + qq;
      midA[i] = ((unsigned)gh < HH && (unsigned)gw < WW)
                ? aplane[gh * WW + gw] : -1e30f;
    }
    const float* prer = g_pre[rb] + (size_t)b * PLANE;
    for (int i = tid; i < PREB_FLOATS; i += NTHR) {
      int rr = i / 18, qq = i - rr * 18;
      int gh = bh - 1 + rr, gw = bw - 1 + qq;
      preb[i] = ((unsigned)gh < HH && (unsigned)gw < WW)
                ? prer[gh * WW + gw] : 0.f;
    }
  }
  __syncthreads();

  // ---- gate = alive_pre & (maxpool3(mid alpha) > 0.1) on the 18x18 ring ----
  if (t > 0) {
    for (int i = tid; i < GA_FLOATS; i += NTHR) {
      int rr = i / 18, qq = i - rr * 18;
      float m = -1e30f;
#pragma unroll
      for (int dr = 0; dr < 3; dr++)
#pragma unroll
        for (int dq = 0; dq < 3; dq++)
          m = fmaxf(m, midA[(rr + dr) * 20 + qq + dq]);
      ga[i] = (preb[i] != 0.f && m > 0.1f) ? 1.f : 0.f;
    }
  }
  __syncthreads();

  // ---- build x_t tile (gated); interior also written as frame t-1 ----
  const float* srcb = (t == 0)
      ? (x0in + (size_t)b * SDIM * PLANE)
      : (g_mid[rb] + (size_t)b * SDIM * PLANE);
  for (int i = tid; i < XS_FLOATS; i += NTHR) {
    int c = i / 324;
    int rem = i - c * 324;
    int r = rem / 18, q = rem - r * 18;
    int gh = bh - 1 + r, gw = bw - 1 + q;
    float v = 0.f;
    if ((unsigned)gh < HH && (unsigned)gw < WW) {
      size_t gi = (size_t)c * PLANE + gh * WW + gw;
      v = srcb[gi];
      if (t > 0) {
        v *= ga[rem];
        if ((unsigned)(r - 1) < 16u && (unsigned)(q - 1) < 16u)
          frame_prev[(size_t)b * SDIM * PLANE + gi] = v;
      }
    }
    xs[i] = v;
  }
  __syncthreads();

  // ---- alive_pre for this step (from gated x_t alpha), both pixels ----
  const uint32_t pixA = (uint32_t)((bh + ty) * WW + (bw + tx));
  const uint32_t pixB = pixA + 8u * WW;
  {
    const float* pa = xs + 3 * 324;
    float mA = -1e30f, mB = -1e30f;
#pragma unroll
    for (int dr = 0; dr < 3; dr++)
#pragma unroll
      for (int dq = 0; dq < 3; dq++) {
        mA = fmaxf(mA, pa[(ty + dr) * 18 + tx + dq]);
        mB = fmaxf(mB, pa[(ty + 8 + dr) * 18 + tx + dq]);
      }
    g_pre[wb][(size_t)b * PLANE + pixA] = (mA > 0.1f) ? 1.f : 0.f;
    g_pre[wb][(size_t)b * PLANE + pixB] = (mB > 0.1f) ? 1.f : 0.f;
  }

  // ---- perception for both pixels ----
  u64 YA[24], YB[24];
#pragma unroll
  for (int c = 0; c < SDIM; c++) {
    {
      const float* p = xs + c * 324 + ty * 18 + tx;
      float a00 = p[0],  a01 = p[1],  a02 = p[2];
      float a10 = p[18], a11 = p[19], a12 = p[20];
      float a20 = p[36], a21 = p[37], a22 = p[38];
      float s1 = ((a02 - a00) + 2.f * (a12 - a10) + (a22 - a20)) * 0.125f;
      float s2 = ((a20 - a00) + 2.f * (a21 - a01) + (a22 - a02)) * 0.125f;
      // y indices 3c, 3c+1, 3c+2 -> packed pairs
      int i0 = 3 * c;
      if (i0 & 1) { float2 pr = unpk(YA[i0 >> 1]); YA[i0 >> 1] = pk(pr.x, a11); }
      else YA[i0 >> 1] = pk(a11, s1);
      if (i0 & 1) { YA[(i0 >> 1) + 1] = pk(s1, s2); }
      else { float2 pr; pr.x = s2; YA[(i0 >> 1) + 1] = pk(s2, 0.f); }
    }
  }
  // The odd/even packing above is hard to express per-channel; rebuild cleanly:
  {
    float y[48];
#pragma unroll
    for (int c = 0; c < SDIM; c++) {
      const float* p = xs + c * 324 + ty * 18 + tx;
      float a00 = p[0],  a01 = p[1],  a02 = p[2];
      float a10 = p[18], a11 = p[19], a12 = p[20];
      float a20 = p[36], a21 = p[37], a22 = p[38];
      y[3 * c]     = a11;
      y[3 * c + 1] = ((a02 - a00) + 2.f * (a12 - a10) + (a22 - a20)) * 0.125f;
      y[3 * c + 2] = ((a20 - a00) + 2.f * (a21 - a01) + (a22 - a02)) * 0.125f;
    }
#pragma unroll
    for (int i = 0; i < 24; i++) YA[i] = pk(y[2 * i], y[2 * i + 1]);
#pragma unroll
    for (int c = 0; c < SDIM; c++) {
      const float* p = xs + c * 324 + (ty + 8) * 18 + tx;
      float a00 = p[0],  a01 = p[1],  a02 = p[2];
      float a10 = p[18], a11 = p[19], a12 = p[20];
      float a20 = p[36], a21 = p[37], a22 = p[38];
      y[3 * c]     = a11;
      y[3 * c + 1] = ((a02 - a00) + 2.f * (a12 - a10) + (a22 - a20)) * 0.125f;
      y[3 * c + 2] = ((a20 - a00) + 2.f * (a21 - a01) + (a22 - a02)) * 0.125f;
    }
#pragma unroll
    for (int i = 0; i < 24; i++) YB[i] = pk(y[2 * i], y[2 * i + 1]);
  }

  // ---- fused matvecs, 2 pixels share every weight load ----
  u64 DA[16], DB[16];
#pragma unroll
  for (int c = 0; c < 16; c++) { DA[c] = 0ull; DB[c] = 0ull; }

#pragma unroll 1
  for (int o = 0; o < HDIM; o += 4) {
    const ulonglong2* r0 = (const ulonglong2*)(w2s + (o + 0) * 48);
    const ulonglong2* r1 = (const ulonglong2*)(w2s + (o + 1) * 48);
    const ulonglong2* r2 = (const ulonglong2*)(w2s + (o + 2) * 48);
    const ulonglong2* r3 = (const ulonglong2*)(w2s + (o + 3) * 48);
    u64 aA0 = 0ull, aA1 = 0ull, aA2 = 0ull, aA3 = 0ull;
    u64 aB0 = 0ull, aB1 = 0ull, aB2 = 0ull, aB3 = 0ull;
#pragma unroll
    for (int kq = 0; kq < 12; kq++) {
      ulonglong2 b0 = r0[kq], b1 = r1[kq], b2 = r2[kq], b3 = r3[kq];
      u64 yAl = YA[2 * kq], yAh = YA[2 * kq + 1];
      u64 yBl = YB[2 * kq], yBh = YB[2 * kq + 1];
      ffma2(aA0, b0.x, yAl); ffma2(aA0, b0.y, yAh);
      ffma2(aB0, b0.x, yBl); ffma2(aB0, b0.y, yBh);
      ffma2(aA1, b1.x, yAl); ffma2(aA1, b1.y, yAh);
      ffma2(aB1, b1.x, yBl); ffma2(aB1, b1.y, yBh);
      ffma2(aA2, b2.x, yAl); ffma2(aA2, b2.y, yAh);
      ffma2(aB2, b2.x, yBl); ffma2(aB2, b2.y, yBh);
      ffma2(aA3, b3.x, yAl); ffma2(aA3, b3.y, yAh);
      ffma2(aB3, b3.x, yBl); ffma2(aB3, b3.y, yBh);
    }
    float2 fA0 = unpk(aA0), fA1 = unpk(aA1), fA2 = unpk(aA2), fA3 = unpk(aA3);
    float2 fB0 = unpk(aB0), fB1 = unpk(aB1), fB2 = unpk(aB2), fB3 = unpk(aB3);
    u64 HA0 = pk(fmaxf(fA0.x + fA0.y, 0.f), fmaxf(fA1.x + fA1.y, 0.f));
    u64 HA1 = pk(fmaxf(fA2.x + fA2.y, 0.f), fmaxf(fA3.x + fA3.y, 0.f));
    u64 HB0 = pk(fmaxf(fB0.x + fB0.y, 0.f), fmaxf(fB1.x + fB1.y, 0.f));
    u64 HB1 = pk(fmaxf(fB2.x + fB2.y, 0.f), fmaxf(fB3.x + fB3.y, 0.f));
#pragma unroll
    for (int c = 0; c < 16; c++) {
      ulonglong2 w = *(const ulonglong2*)(w3s + c * HDIM + o);
      ffma2(DA[c], w.x, HA0); ffma2(DA[c], w.y, HA1);
      ffma2(DB[c], w.x, HB0); ffma2(DB[c], w.y, HB1);
    }
  }

  // ---- stochastic update, write mid_t for both pixels ----
  float* midw = g_mid[wb] + (size_t)b * SDIM * PLANE;
#pragma unroll
  for (int c = 0; c < 16; c++) {
    float2 dA = unpk(DA[c]);
    float vA = xs[c * 324 + (ty + 1) * 18 + (tx + 1)]
             + (((maskA >> c) & 1u) ? (dA.x + dA.y) : 0.f);
    midw[(size_t)c * PLANE + pixA] = vA;
    float2 dB = unpk(DB[c]);
    float vB = xs[c * 324 + (ty + 9) * 18 + (tx + 1)]
             + (((maskB >> c) & 1u) ? (dB.x + dB.y) : 0.f);
    midw[(size_t)c * PLANE + pixB] = vB;
  }
}

// ---------------------------------------------------------------------------
// stepC: gate and emit the final frame.
// ---------------------------------------------------------------------------
extern "C" __global__ void __launch_bounds__(256)
stepC(float* __restrict__ outf, int pb)
{
  int p = blockIdx.x * 256 + threadIdx.x;
  if (p >= NB * PLANE) return;
  int b = p / PLANE;
  int hw = p - b * PLANE;
  int h = hw / WW, w = hw - h * WW;

  const float* mida = g_mid[pb] + ((size_t)b * SDIM + 3) * PLANE;
  float m = -1e30f;
#pragma unroll
  for (int di = -1; di <= 1; di++) {
    int hh = h + di;
    if ((unsigned)hh >= HH) continue;
#pragma unroll
    for (int dj = -1; dj <= 1; dj++) {
      int wq = w + dj;
      if ((unsigned)wq >= WW) continue;
      m = fmaxf(m, mida[hh * WW + wq]);
    }
  }
  float gate = (g_pre[pb][p] != 0.f && m > 0.1f) ? 1.f : 0.f;

  size_t base = (size_t)b * SDIM * PLANE + (size_t)hw;
#pragma unroll
  for (int c = 0; c < 16; c++)
    outf[base + c * PLANE] = g_mid[pb][base + c * PLANE] * gate;
}

// ---------------------------------------------------------------------------
// kernel_launch
// ---------------------------------------------------------------------------
extern "C" void kernel_launch(void* const* d_in, const int* in_sizes, int n_in,
                              void* d_out, int out_size)
{
  const float* x0 = (const float*)d_in[0];
  const float* w2 = (const float*)d_in[3];
  const float* w3 = (const float*)d_in[4];
  float* out = (float*)d_out;

  const int nsteps = out_size / FRAME;

  cudaFuncSetAttribute(stepA, cudaFuncAttributeMaxDynamicSharedMemorySize, SMEM_BYTES);

  for (int t = 0; t < nsteps; t++) {
    uint32_t sk0, sk1;
    threefry2x32(0u, 42u, 0u, (uint32_t)t, sk0, sk1);   // key_t = fold(key42, t)
    float* fprev = out + (size_t)(t > 0 ? t - 1 : 0) * FRAME;
    stepA<<<dim3(6, 6, NB), dim3(16, 8), SMEM_BYTES>>>(x0, w2, w3, fprev, t, sk0, sk1);
  }
  stepC<<<(NB * PLANE + 255) / 256, 256>>>(out + (size_t)(nsteps - 1) * FRAME,
                                           (nsteps - 1) & 1);
}